// round 15
// baseline (speedup 1.0000x reference)
#include <cuda_runtime.h>
#include <cuda_bf16.h>
#include <cstdint>

// Problem constants (fixed by reference setup_inputs)
#define BATCH 4096
#define CELL  400
#define CELL4 100    // CELL/4
#define KMIX  10
#define TLEN  256
#define VDIM  80
#define NT    320    // 10 warps == KMIX warps; 320 = 16 rows x 20 float4-cols

// Whole job streamed via cp.async: 16 chunks x NT float4 = 80KB, 8 commit groups.
// Thread tid's chunk-m element soh[m*NT + tid] == oh[(t0+16m)*20 + c] — each
// thread consumes exactly what it prefetched => no barriers in the stream.
#define SMEM_F4_SOH   (16 * NT)
#define SMEM_BYTES    (SMEM_F4_SOH * 16 + TLEN * 4 + NT * 16 + 32 * 4)

#define CP_ASYNC_16(s, g) \
    asm volatile("cp.async.cg.shared.global [%0], [%1], 16;" :: "r"(s), "l"(g))
#define CP_COMMIT() asm volatile("cp.async.commit_group;" ::: "memory")

__global__ __launch_bounds__(NT)
void window_qstream(const float* __restrict__ x,
                    const float* __restrict__ kappa_old,
                    const float* __restrict__ onehots,
                    const float* __restrict__ W,
                    const float* __restrict__ bias,
                    float* __restrict__ out_weight,   // [B, V]
                    float* __restrict__ out_kappa)    // [B, K]
{
    extern __shared__ float4 dsm[];
    float4* soh   = dsm;                                  // [16*NT] float4 (80KB)
    float*  sphi  = (float*)(dsm + SMEM_F4_SOH);          // [256]
    float4* wpart = (float4*)(sphi + TLEN);               // [NT] float4
    float*  sabk  = (float*)(wpart + NT);                 // [32]

    const int b    = blockIdx.x;
    const int tid  = threadIdx.x;
    const int warp = tid >> 5;
    const int lane = tid & 31;
    const int c    = tid % 20;
    const int t0   = tid / 20;

    const float4*  oh    = (const float4*)(onehots + (size_t)b * TLEN * VDIM);
    const uint32_t soh_u = (uint32_t)__cvta_generic_to_shared(soh);

    // ---- issue the ENTIRE job as cp.async immediately: 16 chunks, 8 groups ----
    #pragma unroll
    for (int k = 0; k < 16; k++) {
        CP_ASYNC_16(soh_u + (uint32_t)(k * NT + tid) * 16, oh + k * NT + tid);
        if (k & 1) CP_COMMIT();
    }

    // ---- prologue: mat-vec (warp w owns component w) + transforms ----
    {
        const float4* x4 = (const float4*)(x + (size_t)b * CELL);
        const float4* W4 = (const float4*)W;
        float s0 = 0.f, s1 = 0.f, s2 = 0.f;
        #pragma unroll 4
        for (int c4 = lane; c4 < CELL4; c4 += 32) {
            const float4 xv = x4[c4];
            const float4 w0 = W4[(warp)          * CELL4 + c4];
            const float4 w1 = W4[(warp + KMIX)   * CELL4 + c4];
            const float4 w2 = W4[(warp + 2*KMIX) * CELL4 + c4];
            s0 += xv.x * w0.x + xv.y * w0.y + xv.z * w0.z + xv.w * w0.w;
            s1 += xv.x * w1.x + xv.y * w1.y + xv.z * w1.z + xv.w * w1.w;
            s2 += xv.x * w2.x + xv.y * w2.y + xv.z * w2.z + xv.w * w2.w;
        }
        #pragma unroll
        for (int off = 16; off > 0; off >>= 1) {
            s0 += __shfl_xor_sync(0xffffffffu, s0, off);
            s1 += __shfl_xor_sync(0xffffffffu, s1, off);
            s2 += __shfl_xor_sync(0xffffffffu, s2, off);
        }
        if (lane == 0) {
            const float kap = kappa_old[(size_t)b * KMIX + warp]
                            + __expf(s2 + bias[warp + 2*KMIX]);
            sabk[warp]          = __expf(s0 + bias[warp]);
            sabk[warp + KMIX]   = __expf(s1 + bias[warp + KMIX]);
            sabk[warp + 2*KMIX] = kap;
            out_kappa[(size_t)b * KMIX + warp] = kap;
        }
    }
    __syncthreads();

    // ---- phi[t] ----
    if (tid < TLEN) {
        const float u = (float)tid;
        float s = 0.0f;
        #pragma unroll
        for (int k = 0; k < KMIX; k++) {
            const float d = sabk[2*KMIX + k] - u;
            s += sabk[k] * __expf(-sabk[KMIX + k] * d * d);
        }
        sphi[tid] = s;
    }
    __syncthreads();   // sphi visible to all

    // ---- barrier-free consumption: pair m after wait_group (7-m) ----
    float4 acc = make_float4(0.f, 0.f, 0.f, 0.f);

    #define CONSUME_PAIR(M, WG)                                             \
        do {                                                                \
            asm volatile("cp.async.wait_group " #WG ";" ::: "memory");      \
            _Pragma("unroll")                                               \
            for (int _h = 0; _h < 2; _h++) {                                \
                const int _m = 2 * (M) + _h;                                \
                const float  _p = sphi[t0 + _m * 16];                       \
                const float4 _o = soh[_m * NT + tid];                       \
                acc.x += _p * _o.x; acc.y += _p * _o.y;                     \
                acc.z += _p * _o.z; acc.w += _p * _o.w;                     \
            }                                                               \
        } while (0)

    CONSUME_PAIR(0, 7);
    CONSUME_PAIR(1, 6);
    CONSUME_PAIR(2, 5);
    CONSUME_PAIR(3, 4);
    CONSUME_PAIR(4, 3);
    CONSUME_PAIR(5, 2);
    CONSUME_PAIR(6, 1);
    CONSUME_PAIR(7, 0);
    #undef CONSUME_PAIR

    wpart[t0 * 20 + c] = acc;
    __syncthreads();

    if (tid < VDIM) {
        const float* wp = (const float*)wpart;
        float s = 0.0f;
        #pragma unroll
        for (int j = 0; j < 16; j++) s += wp[j * VDIM + tid];
        out_weight[(size_t)b * VDIM + tid] = s;
    }
}

extern "C" void kernel_launch(void* const* d_in, const int* in_sizes, int n_in,
                              void* d_out, int out_size)
{
    const float* x         = (const float*)d_in[0];   // [B, CELL]
    const float* kappa_old = (const float*)d_in[1];   // [B, K]
    const float* onehots   = (const float*)d_in[2];   // [B, T, V]
    const float* W         = (const float*)d_in[3];   // [3K, CELL]
    const float* bias      = (const float*)d_in[4];   // [3K]

    float* out_weight = (float*)d_out;                        // [B, V]
    float* out_kappa  = (float*)d_out + (size_t)BATCH * VDIM; // [B, K]

    // ~86KB dynamic smem (needs opt-in; host attribute set is capture-safe,
    // proven rounds 3-7 and 12). 2 CTAs/SM by design: MLP lives in the
    // cp.async queue (160KB in flight per SM), not in warp count.
    cudaFuncSetAttribute(window_qstream,
                         cudaFuncAttributeMaxDynamicSharedMemorySize, SMEM_BYTES);

    window_qstream<<<BATCH, NT, SMEM_BYTES>>>(x, kappa_old, onehots, W, bias,
                                              out_weight, out_kappa);
}

// round 16
// speedup vs baseline: 1.1504x; 1.1504x over previous
#include <cuda_runtime.h>
#include <cuda_bf16.h>
#include <cstdint>

// Problem constants (fixed by reference setup_inputs)
#define BATCH 4096
#define CELL  400
#define CELL4 100    // CELL/4
#define KMIX  10
#define TLEN  256
#define VDIM  80
#define NT    320    // 10 warps
#define RPG   8      // rows per param group
#define NPARM (BATCH / RPG)   // 512 param blocks (bids 0..511, dispatched first)
#define GRID  (NPARM + BATCH)

// abk scratch: per row, stride 32: [alpha 0..9 | beta 0..9 | kappa 0..9 | pad]
__device__ float    g_abk[(size_t)BATCH * 32];
__device__ unsigned g_flag[NPARM];      // release flag per group (reset by consumers)
__device__ unsigned g_consumed[NPARM];  // 8-way consume counter (self-reset)

__global__ __launch_bounds__(NT)
void window_mixed(const float* __restrict__ x,
                  const float* __restrict__ kappa_old,
                  const float* __restrict__ onehots,
                  const float* __restrict__ W,
                  const float* __restrict__ bias,
                  float* __restrict__ out_weight,   // [B, V]
                  float* __restrict__ out_kappa)    // [B, K]
{
    const int tid  = threadIdx.x;
    const int warp = tid >> 5;
    const int lane = tid & 31;

    if (blockIdx.x < NPARM) {
        // ================= param worker: 8 rows, warp w owns component w ======
        const int g  = blockIdx.x;
        const int b0 = g * RPG;
        const float4* W4 = (const float4*)W;
        const float bw0 = bias[warp];
        const float bw1 = bias[warp + KMIX];
        const float bw2 = bias[warp + 2 * KMIX];

        for (int r = 0; r < RPG; r++) {
            const int row = b0 + r;
            const float4* x4 = (const float4*)(x + (size_t)row * CELL);
            float s0 = 0.f, s1 = 0.f, s2 = 0.f;
            #pragma unroll 4
            for (int c4 = lane; c4 < CELL4; c4 += 32) {
                const float4 xv = x4[c4];
                const float4 w0 = W4[(warp)          * CELL4 + c4];
                const float4 w1 = W4[(warp + KMIX)   * CELL4 + c4];
                const float4 w2 = W4[(warp + 2*KMIX) * CELL4 + c4];
                s0 += xv.x * w0.x + xv.y * w0.y + xv.z * w0.z + xv.w * w0.w;
                s1 += xv.x * w1.x + xv.y * w1.y + xv.z * w1.z + xv.w * w1.w;
                s2 += xv.x * w2.x + xv.y * w2.y + xv.z * w2.z + xv.w * w2.w;
            }
            #pragma unroll
            for (int off = 16; off > 0; off >>= 1) {
                s0 += __shfl_xor_sync(0xffffffffu, s0, off);
                s1 += __shfl_xor_sync(0xffffffffu, s1, off);
                s2 += __shfl_xor_sync(0xffffffffu, s2, off);
            }
            if (lane == 0) {
                const float kap = kappa_old[(size_t)row * KMIX + warp] + __expf(s2 + bw2);
                float* dst = g_abk + (size_t)row * 32;
                dst[warp]            = __expf(s0 + bw0);
                dst[warp + KMIX]     = __expf(s1 + bw1);
                dst[warp + 2 * KMIX] = kap;
                out_kappa[(size_t)row * KMIX + warp] = kap;
            }
        }
        __syncthreads();
        if (tid == 0) {
            __threadfence();                  // publish g_abk before the flag
            atomicExch(&g_flag[g], 1u);
        }
        return;
    }

    // ================= stream worker: proven R7 shape + flag gate =============
    const int b = blockIdx.x - NPARM;
    const int g = b >> 3;

    __shared__ float  sabk[32];
    __shared__ float  sphi[TLEN];
    __shared__ float4 wpart[16 * 20];

    if (tid == 0) {
        // spin until the param group publishes (params occupy the lowest bids,
        // depend on nothing, and always complete -> no deadlock)
        while (atomicAdd(&g_flag[g], 0u) == 0u) { __nanosleep(32); }
    }
    __syncthreads();

    if (tid < 3 * KMIX) sabk[tid] = g_abk[(size_t)b * 32 + tid];
    __syncthreads();

    if (tid < TLEN) {
        const float u = (float)tid;
        float s = 0.0f;
        #pragma unroll
        for (int k = 0; k < KMIX; k++) {
            const float d = sabk[2 * KMIX + k] - u;
            s += sabk[k] * __expf(-sabk[KMIX + k] * d * d);
        }
        sphi[tid] = s;
    }
    __syncthreads();

    // self-reset scheduler state for deterministic graph replays:
    // the 8th consumer of group g clears the flag + counter
    if (tid == 0) {
        if (atomicAdd(&g_consumed[g], 1u) == 7u) {
            g_consumed[g] = 0u;
            g_flag[g]     = 0u;
        }
    }

    // ---- streaming einsum (proven: float4, coalesced, 82-85% DRAM) ----
    const float4* oh = (const float4*)(onehots + (size_t)b * TLEN * VDIM);
    const int c  = tid % 20;    // float4 column (v/4)
    const int t0 = tid / 20;    // 0..15

    float4 acc = make_float4(0.f, 0.f, 0.f, 0.f);
    #pragma unroll
    for (int j = 0; j < 16; j++) {
        const int t = t0 + j * 16;
        const float  p = sphi[t];
        const float4 o = oh[t * 20 + c];
        acc.x += p * o.x; acc.y += p * o.y; acc.z += p * o.z; acc.w += p * o.w;
    }
    wpart[t0 * 20 + c] = acc;
    __syncthreads();

    if (tid < VDIM) {
        const float* wp = (const float*)wpart;
        float s = 0.0f;
        #pragma unroll
        for (int j = 0; j < 16; j++) s += wp[j * VDIM + tid];
        out_weight[(size_t)b * VDIM + tid] = s;
    }
}

extern "C" void kernel_launch(void* const* d_in, const int* in_sizes, int n_in,
                              void* d_out, int out_size)
{
    const float* x         = (const float*)d_in[0];   // [B, CELL]
    const float* kappa_old = (const float*)d_in[1];   // [B, K]
    const float* onehots   = (const float*)d_in[2];   // [B, T, V]
    const float* W         = (const float*)d_in[3];   // [3K, CELL]
    const float* bias      = (const float*)d_in[4];   // [3K]

    float* out_weight = (float*)d_out;                        // [B, V]
    float* out_kappa  = (float*)d_out + (size_t)BATCH * VDIM; // [B, K]

    window_mixed<<<GRID, NT>>>(x, kappa_old, onehots, W, bias,
                               out_weight, out_kappa);
}